// round 6
// baseline (speedup 1.0000x reference)
#include <cuda_runtime.h>
#include <cuda_bf16.h>

#define PADDING_IDX 0
#define SMOOTHING   0.1f
#define GRID_BLOCKS 1024          // <= 1184 resident (148 SMs x 8 blocks @256thr): ONE wave
#define MAX_PART    4096

// Per-block partial contributions. __device__ global: allocation-free.
__device__ float g_block_partial[MAX_PART];

// Persistent-style: each block owns `rpb` consecutive rows, streams them all,
// does ONE block reduction at the end. Gathers are prefetched at block start
// (independent loads, hidden behind ~512KB of streaming).
// total = -(S/V) * sum_{valid rows} rowsum  -  (1-S) * sum_{valid rows} x[r, t_r]
// NOTE: target is int32 on device (JAX x64-disabled downcasts int64 -> int32).
__global__ void __launch_bounds__(256)
ls_row_kernel(const float* __restrict__ x,
              const int* __restrict__ target,
              int V, int N)
{
    const int rpb = (N + gridDim.x - 1) / gridDim.x;
    const int r0  = blockIdx.x * rpb;
    const int r1  = (r0 + rpb < N) ? (r0 + rpb) : N;
    const int nrows = r1 - r0;

    // ---- prefetch gathers: thread k handles row r0+k ----
    float gs = 0.0f;
    if (threadIdx.x < nrows) {
        const int r = r0 + threadIdx.x;
        const int t = target[r];
        if (t != PADDING_IDX && t > 0 && t < V)
            gs = x[(size_t)r * (size_t)V + (size_t)t];  // issued now, consumed at the end
    }

    // ---- stream all valid rows, one thread-local accumulator set ----
    float s0 = 0.0f, s1 = 0.0f, s2 = 0.0f, s3 = 0.0f;
    const int nv4 = V >> 2;                         // 32000 -> 8000 float4/row

    for (int r = r0; r < r1; r++) {
        const int t = target[r];                    // broadcast load, L2-hot
        if (t == PADDING_IDX || t < 0 || t >= V) continue;   // masked row: skip entirely

        const float4* __restrict__ row4 =
            reinterpret_cast<const float4*>(x + (size_t)r * (size_t)V);

        int i = threadIdx.x;
        // Unroll-4: 4 independent 16B streaming loads in flight per thread.
        for (; i + 768 < nv4; i += 1024) {
            float4 a = __ldcs(&row4[i]);
            float4 b = __ldcs(&row4[i + 256]);
            float4 c = __ldcs(&row4[i + 512]);
            float4 d = __ldcs(&row4[i + 768]);
            s0 += (a.x + a.y) + (a.z + a.w);
            s1 += (b.x + b.y) + (b.z + b.w);
            s2 += (c.x + c.y) + (c.z + c.w);
            s3 += (d.x + d.y) + (d.z + d.w);
        }
        for (; i < nv4; i += 256) {
            float4 a = __ldcs(&row4[i]);
            s0 += (a.x + a.y) + (a.z + a.w);
        }
        for (int j = (nv4 << 2) + threadIdx.x; j < V; j += 256)
            s0 += x[(size_t)r * (size_t)V + j];     // tail (unused for V=32000)
    }
    float s = (s0 + s1) + (s2 + s3);

    // ---- ONE block reduction of (s, gs) ----
    #pragma unroll
    for (int o = 16; o > 0; o >>= 1) {
        s  += __shfl_down_sync(0xffffffffu, s,  o);
        gs += __shfl_down_sync(0xffffffffu, gs, o);
    }
    __shared__ float shs[8], shg[8];
    if ((threadIdx.x & 31) == 0) {
        shs[threadIdx.x >> 5] = s;
        shg[threadIdx.x >> 5] = gs;
    }
    __syncthreads();

    if (threadIdx.x < 32) {
        float vs = (threadIdx.x < 8) ? shs[threadIdx.x] : 0.0f;
        float vg = (threadIdx.x < 8) ? shg[threadIdx.x] : 0.0f;
        #pragma unroll
        for (int o = 4; o > 0; o >>= 1) {
            vs += __shfl_down_sync(0xffffffffu, vs, o);
            vg += __shfl_down_sync(0xffffffffu, vg, o);
        }
        if (threadIdx.x == 0)
            g_block_partial[blockIdx.x] =
                -(SMOOTHING / (float)V) * vs - (1.0f - SMOOTHING) * vg;
    }
    __syncthreads();   // publish before PDL trigger

    asm volatile("griddepcontrol.launch_dependents;" ::: "memory");
}

// Deterministic single-block reduction of nblk block partials -> scalar.
__global__ void __launch_bounds__(256)
ls_final_kernel(float* __restrict__ out, int nblk)
{
    asm volatile("griddepcontrol.wait;" ::: "memory");

    const float4* __restrict__ p4 = reinterpret_cast<const float4*>(g_block_partial);
    const int n4 = nblk >> 2;                       // 1024 -> 256 float4

    float s = 0.0f;
    for (int i = threadIdx.x; i < n4; i += 256) {
        float4 v = p4[i];
        s += (v.x + v.y) + (v.z + v.w);
    }
    for (int i = (n4 << 2) + threadIdx.x; i < nblk; i += 256)
        s += g_block_partial[i];

    #pragma unroll
    for (int o = 16; o > 0; o >>= 1)
        s += __shfl_down_sync(0xffffffffu, s, o);

    __shared__ float sh[8];
    if ((threadIdx.x & 31) == 0) sh[threadIdx.x >> 5] = s;
    __syncthreads();

    if (threadIdx.x < 32) {
        float v = (threadIdx.x < 8) ? sh[threadIdx.x] : 0.0f;
        #pragma unroll
        for (int o = 4; o > 0; o >>= 1)
            v += __shfl_down_sync(0xffffffffu, v, o);
        if (threadIdx.x == 0) out[0] = v;
    }
}

extern "C" void kernel_launch(void* const* d_in, const int* in_sizes, int n_in,
                              void* d_out, int out_size)
{
    const float* x      = (const float*)d_in[0];
    const int*   target = (const int*)d_in[1];
    float*       out    = (float*)d_out;

    const int N = in_sizes[1];         // 4096 rows
    const int V = in_sizes[0] / N;     // 32000 vocab

    const int grid = (N < GRID_BLOCKS) ? N : GRID_BLOCKS;
    ls_row_kernel<<<grid, 256>>>(x, target, V, N);

    cudaLaunchConfig_t cfg = {};
    cfg.gridDim  = dim3(1, 1, 1);
    cfg.blockDim = dim3(256, 1, 1);
    cfg.dynamicSmemBytes = 0;
    cudaLaunchAttribute attr[1];
    attr[0].id = cudaLaunchAttributeProgrammaticStreamSerialization;
    attr[0].val.programmaticStreamSerializationAllowed = 1;
    cfg.attrs = attr;
    cfg.numAttrs = 1;
    cudaLaunchKernelEx(&cfg, ls_final_kernel, out, grid);
}

// round 7
// speedup vs baseline: 1.1261x; 1.1261x over previous
#include <cuda_runtime.h>
#include <cuda_bf16.h>

#define PADDING_IDX 0
#define SMOOTHING   0.1f
#define MAX_ROWS    8192

// __device__ globals: allocation-free per harness rules.
__device__ float        g_row_partial[MAX_ROWS];
__device__ unsigned int g_done = 0;   // reset by the spinner block each launch

// grid = N+1. Blocks [0,N): one row each (R4's proven layout, 3.46 waves,
// work-stealing balanced). Block N: spinner that waits for all N partials
// (acquire-poll on g_done) and produces the scalar — replaces the 4.4us
// dependent final-kernel node with ~1us of in-kernel tail.
// NOTE: target is int32 on device (JAX x64-disabled downcasts int64 -> int32).
__global__ void __launch_bounds__(256)
ls_kernel(const float* __restrict__ x,
          const int* __restrict__ target,
          float* __restrict__ out,
          int V, int N)
{
    __shared__ float sh[8];

    if (blockIdx.x < (unsigned)N) {
        // ---------------- worker: stream one row ----------------
        const int r = blockIdx.x;
        const int t = target[r];

        if (t == PADDING_IDX || t < 0 || t >= V) {
            if (threadIdx.x == 0) {
                g_row_partial[r] = 0.0f;
                // release: partial store visible before the increment is
                asm volatile("red.release.gpu.global.add.u32 [%0], %1;"
                             :: "l"(&g_done), "r"(1u) : "memory");
            }
            return;
        }

        const size_t row_off = (size_t)r * (size_t)V;
        const float4* __restrict__ row4 = reinterpret_cast<const float4*>(x + row_off);
        const int nv4 = V >> 2;                      // 32000 -> 8000 float4

        float s = 0.0f;
        // Coalesced 128B wavefronts, ~31 iters/thread -> deep MLP.
        for (int i = threadIdx.x; i < nv4; i += blockDim.x) {
            float4 v = row4[i];
            s += (v.x + v.y) + (v.z + v.w);
        }
        for (int i = (nv4 << 2) + threadIdx.x; i < V; i += blockDim.x)
            s += x[row_off + i];                     // tail (unused for V=32000)

        #pragma unroll
        for (int o = 16; o > 0; o >>= 1)
            s += __shfl_down_sync(0xffffffffu, s, o);
        if ((threadIdx.x & 31) == 0) sh[threadIdx.x >> 5] = s;
        __syncthreads();

        if (threadIdx.x < 32) {
            float v = (threadIdx.x < 8) ? sh[threadIdx.x] : 0.0f;
            #pragma unroll
            for (int o = 4; o > 0; o >>= 1)
                v += __shfl_down_sync(0xffffffffu, v, o);
            if (threadIdx.x == 0) {
                const float g = x[row_off + (size_t)t];   // gather, L2-hot
                g_row_partial[r] = -(SMOOTHING / (float)V) * v - (1.0f - SMOOTHING) * g;
                asm volatile("red.release.gpu.global.add.u32 [%0], %1;"
                             :: "l"(&g_done), "r"(1u) : "memory");
            }
        }
        return;
    }

    // ---------------- spinner: final reduction ----------------
    // Workers never depend on this block -> no deadlock regardless of wave.
    if (threadIdx.x == 0) {
        unsigned int d;
        do {
            asm volatile("ld.acquire.gpu.global.u32 %0, [%1];"
                         : "=r"(d) : "l"(&g_done) : "memory");
            if (d < (unsigned)N) __nanosleep(1024);   // ~1 poll/us: no L2 pressure
        } while (d < (unsigned)N);
    }
    __syncthreads();   // all 256 threads released after counter hits N

    const float4* __restrict__ p4 = reinterpret_cast<const float4*>(g_row_partial);
    const int n4 = N >> 2;                           // 4096 -> 1024 float4

    float s = 0.0f;
    for (int i = threadIdx.x; i < n4; i += 256) {    // 4 iters, L2-hot
        float4 v = p4[i];
        s += (v.x + v.y) + (v.z + v.w);
    }
    for (int i = (n4 << 2) + threadIdx.x; i < N; i += 256)
        s += g_row_partial[i];

    #pragma unroll
    for (int o = 16; o > 0; o >>= 1)
        s += __shfl_down_sync(0xffffffffu, s, o);
    if ((threadIdx.x & 31) == 0) sh[threadIdx.x >> 5] = s;
    __syncthreads();

    if (threadIdx.x < 32) {
        float v = (threadIdx.x < 8) ? sh[threadIdx.x] : 0.0f;
        #pragma unroll
        for (int o = 4; o > 0; o >>= 1)
            v += __shfl_down_sync(0xffffffffu, v, o);
        if (threadIdx.x == 0) {
            out[0] = v;
            g_done = 0;   // reset for next graph replay (only this block touches it now)
        }
    }
}

extern "C" void kernel_launch(void* const* d_in, const int* in_sizes, int n_in,
                              void* d_out, int out_size)
{
    const float* x      = (const float*)d_in[0];
    const int*   target = (const int*)d_in[1];
    float*       out    = (float*)d_out;

    const int N = in_sizes[1];         // 4096 rows
    const int V = in_sizes[0] / N;     // 32000 vocab

    ls_kernel<<<N + 1, 256>>>(x, target, out, V, N);
}

// round 8
// speedup vs baseline: 1.1520x; 1.0230x over previous
#include <cuda_runtime.h>
#include <cuda_bf16.h>

#define PADDING_IDX 0
#define SMOOTHING   0.1f
#define MAX_ROWS    8192

// Generation-tagged partial slots: {f32 value, u32 gen} in one aligned 8B word.
// A single 8B store publishes both atomically -> NO fences/atomics needed.
// __device__ globals: allocation-free per harness rules.
__device__ unsigned long long g_slot[MAX_ROWS];   // zero-init: gen=0
__device__ unsigned int       g_gen = 0;          // bumped by spinner each launch

__device__ __forceinline__ void slot_store(int r, float v, unsigned int gen) {
    unsigned long long w =
        ((unsigned long long)gen << 32) | (unsigned long long)__float_as_uint(v);
    asm volatile("st.global.volatile.u64 [%0], %1;"
                 :: "l"(&g_slot[r]), "l"(w) : "memory");
}
__device__ __forceinline__ unsigned long long slot_load(int r) {
    unsigned long long w;
    asm volatile("ld.global.volatile.u64 %0, [%1];"
                 : "=l"(w) : "l"(&g_slot[r]) : "memory");
    return w;
}

// grid = N+1. blockIdx 1..N: one row each (R4's proven ceiling-rate streamer,
// worker epilogue = ONE plain 8B store — zero ordering cost). blockIdx 0:
// spinner that polls the gen tags, then does the fixed-order final reduce.
// NOTE: target is int32 on device (JAX x64-disabled downcasts int64 -> int32).
__global__ void __launch_bounds__(256)
ls_kernel(const float* __restrict__ x,
          const int* __restrict__ target,
          float* __restrict__ out,
          int V, int N)
{
    __shared__ float sh[8];
    const unsigned int gen = g_gen + 1u;   // L2-hot broadcast; stable during launch

    if (blockIdx.x != 0) {
        // ---------------- worker: stream one row ----------------
        const int r = blockIdx.x - 1;
        const int t = target[r];

        if (t == PADDING_IDX || t < 0 || t >= V) {
            if (threadIdx.x == 0) slot_store(r, 0.0f, gen);
            return;
        }

        const size_t row_off = (size_t)r * (size_t)V;
        const float4* __restrict__ row4 = reinterpret_cast<const float4*>(x + row_off);
        const int nv4 = V >> 2;                      // 32000 -> 8000 float4

        float s = 0.0f;
        // Coalesced 128B wavefronts, ~31 iters/thread -> deep MLP; at LTS cap.
        for (int i = threadIdx.x; i < nv4; i += blockDim.x) {
            float4 v = row4[i];
            s += (v.x + v.y) + (v.z + v.w);
        }
        for (int i = (nv4 << 2) + threadIdx.x; i < V; i += blockDim.x)
            s += x[row_off + i];                     // tail (unused for V=32000)

        #pragma unroll
        for (int o = 16; o > 0; o >>= 1)
            s += __shfl_down_sync(0xffffffffu, s, o);
        if ((threadIdx.x & 31) == 0) sh[threadIdx.x >> 5] = s;
        __syncthreads();

        if (threadIdx.x < 32) {
            float v = (threadIdx.x < 8) ? sh[threadIdx.x] : 0.0f;
            #pragma unroll
            for (int o = 4; o > 0; o >>= 1)
                v += __shfl_down_sync(0xffffffffu, v, o);
            if (threadIdx.x == 0) {
                const float g = x[row_off + (size_t)t];   // gather, L2-hot
                slot_store(r, -(SMOOTHING / (float)V) * v - (1.0f - SMOOTHING) * g, gen);
            }
        }
        return;
    }

    // ---------------- spinner (block 0): wait + final reduce ----------------
    // Each thread owns slots {tid, tid+256, ...}; polls until its slots carry
    // this launch's gen tag. Workers never depend on this block -> no deadlock.
    float s = 0.0f;
    for (int i = threadIdx.x; i < N; i += 256) {
        unsigned long long w = slot_load(i);
        while ((unsigned int)(w >> 32) != gen) {
            __nanosleep(256);
            w = slot_load(i);
        }
        s += __uint_as_float((unsigned int)w);       // fixed order per thread
    }

    #pragma unroll
    for (int o = 16; o > 0; o >>= 1)
        s += __shfl_down_sync(0xffffffffu, s, o);
    if ((threadIdx.x & 31) == 0) sh[threadIdx.x >> 5] = s;
    __syncthreads();

    if (threadIdx.x < 32) {
        float v = (threadIdx.x < 8) ? sh[threadIdx.x] : 0.0f;
        #pragma unroll
        for (int o = 4; o > 0; o >>= 1)
            v += __shfl_down_sync(0xffffffffu, v, o);
        if (threadIdx.x == 0) {
            out[0] = v;
            g_gen = gen;   // next launch expects gen+1 (kernel-boundary visibility)
        }
    }
}

extern "C" void kernel_launch(void* const* d_in, const int* in_sizes, int n_in,
                              void* d_out, int out_size)
{
    const float* x      = (const float*)d_in[0];
    const int*   target = (const int*)d_in[1];
    float*       out    = (float*)d_out;

    const int N = in_sizes[1];         // 4096 rows
    const int V = in_sizes[0] / N;     // 32000 vocab

    ls_kernel<<<N + 1, 256>>>(x, target, out, V, N);
}

// round 9
// speedup vs baseline: 1.1557x; 1.0032x over previous
#include <cuda_runtime.h>
#include <cuda_bf16.h>

#define PADDING_IDX 0
#define SMOOTHING   0.1f

// Per-half-row partials: 2 blocks per row, N=4096 -> 8192 partials.
// __device__ global: allocation-free per harness rules.
#define MAX_PART 16384
__device__ float g_part[MAX_PART];

// grid = 2*N. Block 2r+h streams half h of row r (64KB granules ~11us):
// small granules let work-stealing absorb per-CTA L1tex-queue spread and
// halve the last-wave straggler cost vs one-block-per-row.
//   partial[2r+0] = -(S/V)*sum(first half)  - (1-S)*x[r,t_r]   (if valid)
//   partial[2r+1] = -(S/V)*sum(second half)                    (if valid)
// NOTE: target is int32 on device (JAX x64-disabled downcasts int64 -> int32).
__global__ void __launch_bounds__(256)
ls_row_kernel(const float* __restrict__ x,
              const int* __restrict__ target,
              int V)
{
    const int blk = blockIdx.x;
    const int r   = blk >> 1;
    const int h   = blk & 1;
    const int t   = target[r];

    if (t == PADDING_IDX || t < 0 || t >= V) {
        if (threadIdx.x == 0) g_part[blk] = 0.0f;
        return;   // masked row: skip streaming entirely
    }

    const size_t row_off = (size_t)r * (size_t)V;
    const float4* __restrict__ row4 = reinterpret_cast<const float4*>(x + row_off);
    const int nv4 = V >> 2;                 // 32000 -> 8000 float4 chunks
    const int c0  = h ? (nv4 >> 1) : 0;     // half boundaries in chunks
    const int c1  = h ? nv4 : (nv4 >> 1);

    float s = 0.0f;
    // Coalesced 128B wavefronts; ~15.6 iters/thread -> MLP still deep.
    for (int i = c0 + threadIdx.x; i < c1; i += blockDim.x) {
        float4 v = row4[i];
        s += (v.x + v.y) + (v.z + v.w);
    }
    if (h == 1)                              // element tail (unused for V=32000)
        for (int j = (nv4 << 2) + threadIdx.x; j < V; j += blockDim.x)
            s += x[row_off + j];

    // Block reduce
    #pragma unroll
    for (int o = 16; o > 0; o >>= 1)
        s += __shfl_down_sync(0xffffffffu, s, o);

    __shared__ float sh[8];
    if ((threadIdx.x & 31) == 0) sh[threadIdx.x >> 5] = s;
    __syncthreads();

    if (threadIdx.x < 32) {
        float v = (threadIdx.x < 8) ? sh[threadIdx.x] : 0.0f;
        #pragma unroll
        for (int o = 4; o > 0; o >>= 1)
            v += __shfl_down_sync(0xffffffffu, v, o);
        if (threadIdx.x == 0) {
            float p = -(SMOOTHING / (float)V) * v;
            if (h == 0)
                p -= (1.0f - SMOOTHING) * x[row_off + (size_t)t];  // gather once per row
            g_part[blk] = p;
        }
    }
}

// Deterministic single-block reduction of n partials -> scalar (L2-hot).
__global__ void __launch_bounds__(256)
ls_final_kernel(float* __restrict__ out, int n)
{
    const float4* __restrict__ p4 = reinterpret_cast<const float4*>(g_part);
    const int n4 = n >> 2;                  // 8192 -> 2048 float4

    float s = 0.0f;
    for (int i = threadIdx.x; i < n4; i += 256) {   // 8 iters
        float4 v = p4[i];
        s += (v.x + v.y) + (v.z + v.w);
    }
    for (int i = (n4 << 2) + threadIdx.x; i < n; i += 256)
        s += g_part[i];

    #pragma unroll
    for (int o = 16; o > 0; o >>= 1)
        s += __shfl_down_sync(0xffffffffu, s, o);

    __shared__ float sh[8];
    if ((threadIdx.x & 31) == 0) sh[threadIdx.x >> 5] = s;
    __syncthreads();

    if (threadIdx.x < 32) {
        float v = (threadIdx.x < 8) ? sh[threadIdx.x] : 0.0f;
        #pragma unroll
        for (int o = 4; o > 0; o >>= 1)
            v += __shfl_down_sync(0xffffffffu, v, o);
        if (threadIdx.x == 0) out[0] = v;
    }
}

extern "C" void kernel_launch(void* const* d_in, const int* in_sizes, int n_in,
                              void* d_out, int out_size)
{
    const float* x      = (const float*)d_in[0];
    const int*   target = (const int*)d_in[1];
    float*       out    = (float*)d_out;

    const int N = in_sizes[1];         // 4096 rows
    const int V = in_sizes[0] / N;     // 32000 vocab

    ls_row_kernel<<<2 * N, 256>>>(x, target, V);
    ls_final_kernel<<<1, 256>>>(out, 2 * N);
}

// round 10
// speedup vs baseline: 1.1626x; 1.0060x over previous
#include <cuda_runtime.h>
#include <cuda_bf16.h>

#define PADDING_IDX 0
#define SMOOTHING   0.1f
#define MAX_ROWS    8192

// Generation-tagged partial slots: {f32 value, u32 gen} in one aligned 8B word.
// One 8B store publishes value+tag atomically -> no fences/atomics anywhere.
// __device__ globals: allocation-free per harness rules.
__device__ unsigned long long g_slot[MAX_ROWS];   // zero-init: gen=0
__device__ unsigned int       g_gen = 0;          // bumped by spinner each launch

__device__ __forceinline__ void slot_store(int r, float v, unsigned int gen) {
    unsigned long long w =
        ((unsigned long long)gen << 32) | (unsigned long long)__float_as_uint(v);
    asm volatile("st.global.volatile.u64 [%0], %1;"
                 :: "l"(&g_slot[r]), "l"(w) : "memory");
}
__device__ __forceinline__ unsigned long long slot_load(int r) {
    unsigned long long w;
    asm volatile("ld.global.volatile.u64 %0, [%1];"
                 : "=l"(w) : "l"(&g_slot[r]) : "memory");
    return w;
}

// grid = N+1. blockIdx 1..N: one row each (proven ceiling-rate streamer,
// epilogue = ONE plain 8B store). blockIdx 0: sweep-spinner that consumes
// partials AS THEY ARRIVE (non-blocking per-slot), so the tail after the
// last worker is ~1 sweep (~1us) instead of a 4.5us dependent kernel.
// Per-thread accumulation order is fixed (slot index order) -> deterministic.
// NOTE: target is int32 on device (JAX x64-disabled downcasts int64 -> int32).
__global__ void __launch_bounds__(256)
ls_kernel(const float* __restrict__ x,
          const int* __restrict__ target,
          float* __restrict__ out,
          int V, int N)
{
    __shared__ float sh[8];
    const unsigned int gen = g_gen + 1u;   // L2-hot broadcast; stable during launch

    if (blockIdx.x != 0) {
        // ---------------- worker: stream one row ----------------
        const int r = blockIdx.x - 1;
        const int t = target[r];

        if (t == PADDING_IDX || t < 0 || t >= V) {
            if (threadIdx.x == 0) slot_store(r, 0.0f, gen);
            return;
        }

        const size_t row_off = (size_t)r * (size_t)V;
        const float4* __restrict__ row4 = reinterpret_cast<const float4*>(x + row_off);
        const int nv4 = V >> 2;                      // 32000 -> 8000 float4

        float s = 0.0f;
        for (int i = threadIdx.x; i < nv4; i += blockDim.x) {
            float4 v = row4[i];
            s += (v.x + v.y) + (v.z + v.w);
        }
        for (int i = (nv4 << 2) + threadIdx.x; i < V; i += blockDim.x)
            s += x[row_off + i];                     // tail (unused for V=32000)

        #pragma unroll
        for (int o = 16; o > 0; o >>= 1)
            s += __shfl_down_sync(0xffffffffu, s, o);
        if ((threadIdx.x & 31) == 0) sh[threadIdx.x >> 5] = s;
        __syncthreads();

        if (threadIdx.x < 32) {
            float v = (threadIdx.x < 8) ? sh[threadIdx.x] : 0.0f;
            #pragma unroll
            for (int o = 4; o > 0; o >>= 1)
                v += __shfl_down_sync(0xffffffffu, v, o);
            if (threadIdx.x == 0) {
                const float g = x[row_off + (size_t)t];   // gather, L2-hot
                slot_store(r, -(SMOOTHING / (float)V) * v - (1.0f - SMOOTHING) * g, gen);
            }
        }
        return;
    }

    // ------------- spinner (block 0): consume-as-ready sweep -------------
    // Thread t owns slots {t, t+256, ..., t+3840}. Accumulation is in fixed
    // slot order per thread via ordered bit-scan of `pend` -> deterministic.
    const int nslots = (N + 255) >> 8;               // 16 for N=4096
    float acc[16];
    #pragma unroll
    for (int k = 0; k < 16; k++) acc[k] = 0.0f;

    unsigned int pend = (nslots >= 32) ? 0xFFFFFFFFu : ((1u << nslots) - 1u);
    // mask off slots beyond N
    #pragma unroll
    for (int k = 0; k < 16; k++)
        if ((int)threadIdx.x + (k << 8) >= N) pend &= ~(1u << k);

    while (pend) {
        unsigned int made = 0;
        #pragma unroll
        for (int k = 0; k < 16; k++) {
            if (pend & (1u << k)) {
                // independent volatile loads across k -> pipelined (MLP)
                unsigned long long w = slot_load(threadIdx.x + (k << 8));
                if ((unsigned int)(w >> 32) == gen) {
                    acc[k] = __uint_as_float((unsigned int)w);
                    pend &= ~(1u << k);
                    made = 1;
                }
            }
        }
        if (!made) __nanosleep(128);                 // back off only if stalled
    }

    // fixed-order per-thread sum, then block reduce
    float s = 0.0f;
    #pragma unroll
    for (int k = 0; k < 16; k++) s += acc[k];

    #pragma unroll
    for (int o = 16; o > 0; o >>= 1)
        s += __shfl_down_sync(0xffffffffu, s, o);
    if ((threadIdx.x & 31) == 0) sh[threadIdx.x >> 5] = s;
    __syncthreads();

    if (threadIdx.x < 32) {
        float v = (threadIdx.x < 8) ? sh[threadIdx.x] : 0.0f;
        #pragma unroll
        for (int o = 4; o > 0; o >>= 1)
            v += __shfl_down_sync(0xffffffffu, v, o);
        if (threadIdx.x == 0) {
            out[0] = v;
            g_gen = gen;   // next replay expects gen+1 (kernel-boundary visibility)
        }
    }
}

extern "C" void kernel_launch(void* const* d_in, const int* in_sizes, int n_in,
                              void* d_out, int out_size)
{
    const float* x      = (const float*)d_in[0];
    const int*   target = (const int*)d_in[1];
    float*       out    = (float*)d_out;

    const int N = in_sizes[1];         // 4096 rows
    const int V = in_sizes[0] / N;     // 32000 vocab

    ls_kernel<<<N + 1, 256>>>(x, target, out, V, N);
}